// round 1
// baseline (speedup 1.0000x reference)
#include <cuda_runtime.h>
#include <math.h>

// SlatewiseGRU: B=128, S=64, K=10, D=256.
// Key simplification: input second half is zeros => threshold mask is dead,
// input-side GEMM (GI) is recurrence-free and hoisted.

static __device__ __forceinline__ unsigned long long pack2(float x, float y) {
    unsigned long long r;
    asm("mov.b64 %0, {%1, %2};" : "=l"(r) : "f"(x), "f"(y));
    return r;
}
static __device__ __forceinline__ unsigned long long fma2(unsigned long long a,
                                                          unsigned long long b,
                                                          unsigned long long c) {
    unsigned long long d;
    asm("fma.rn.f32x2 %0, %1, %2, %3;" : "=l"(d) : "l"(a), "l"(b), "l"(c));
    return d;
}
static __device__ __forceinline__ float2 unpack2(unsigned long long v) {
    float lo, hi;
    asm("mov.b64 {%0, %1}, %2;" : "=f"(lo), "=f"(hi) : "l"(v));
    return make_float2(lo, hi);
}

// Scratch (device globals: allocation-free per harness rules)
__device__ float g_GI[62914560];   // [N*K=81920][768]  precomputed input gates (+biases)
__device__ float g_WihT[196608];   // [256][768]  = W_ih[:, :256]^T
__device__ float g_WhhT[196608];   // [256][768]  = W_hh^T

// ---------------------------------------------------------------------------
// Transpose weights into k-major layout for coalesced GEMM B-tiles.
__global__ void prep_kernel(const float* __restrict__ W_ih,
                            const float* __restrict__ W_hh) {
    int t = blockIdx.x * 256 + threadIdx.x;
    if (t >= 768 * 256) return;
    int j = t >> 8;   // 0..767 (output gate-dim)
    int k = t & 255;  // 0..255 (inner dim)
    g_WihT[k * 768 + j] = W_ih[j * 512 + k];  // only first 256 cols of W_ih matter
    g_WhhT[k * 768 + j] = W_hh[j * 256 + k];
}

// ---------------------------------------------------------------------------
// GI[r, j] = sum_k item[r,k] * W_ih[j,k] + b_ih[j] + (j<512 ? b_hh[j] : 0)
// r over 81920 rows (= n*10+k, matching item_embs memory layout directly).
// BM=128, BN=128, BK=16, 256 threads, per-thread 8x8 via f32x2 pairs.
// A tile stored pre-duplicated ({a,a} packed) so the broadcast operand needs no
// per-FMA packing.
__global__ void __launch_bounds__(256) gi_gemm(const float* __restrict__ A,
                                               const float* __restrict__ b_ih,
                                               const float* __restrict__ b_hh) {
    __shared__ unsigned long long As2[128 * 16];  // [m][k], dup-packed (16KB)
    __shared__ float Bs[16 * 128];                // [k][j]             (8KB)
    const int tid = threadIdx.x;
    const int tx = tid & 15, ty = tid >> 4;
    const int r0 = blockIdx.x * 128;
    const int j0 = blockIdx.y * 128;

    unsigned long long acc[8][4];
#pragma unroll
    for (int i = 0; i < 8; i++)
#pragma unroll
        for (int p = 0; p < 4; p++) acc[i][p] = 0ull;

    for (int k0 = 0; k0 < 256; k0 += 16) {
#pragma unroll
        for (int it = 0; it < 2; it++) {
            int f = tid + it * 256;          // 512 float4 loads of A tile
            int m = f >> 2, kk4 = f & 3;
            float4 v = *(const float4*)(A + (size_t)(r0 + m) * 256 + k0 + kk4 * 4);
            As2[m * 16 + kk4 * 4 + 0] = pack2(v.x, v.x);
            As2[m * 16 + kk4 * 4 + 1] = pack2(v.y, v.y);
            As2[m * 16 + kk4 * 4 + 2] = pack2(v.z, v.z);
            As2[m * 16 + kk4 * 4 + 3] = pack2(v.w, v.w);
        }
#pragma unroll
        for (int it = 0; it < 2; it++) {
            int f = tid + it * 256;          // 512 float4 loads of B tile
            int kk = f >> 5, j4 = f & 31;
            *(float4*)(Bs + kk * 128 + j4 * 4) =
                *(const float4*)(g_WihT + (size_t)(k0 + kk) * 768 + j0 + j4 * 4);
        }
        __syncthreads();
#pragma unroll
        for (int kk = 0; kk < 16; kk++) {
            unsigned long long a[8];
#pragma unroll
            for (int i = 0; i < 8; i++) a[i] = As2[(ty * 8 + i) * 16 + kk];
            ulonglong2 b01 = *(ulonglong2*)(Bs + kk * 128 + tx * 8);
            ulonglong2 b23 = *(ulonglong2*)(Bs + kk * 128 + tx * 8 + 4);
#pragma unroll
            for (int i = 0; i < 8; i++) {
                acc[i][0] = fma2(a[i], b01.x, acc[i][0]);
                acc[i][1] = fma2(a[i], b01.y, acc[i][1]);
                acc[i][2] = fma2(a[i], b23.x, acc[i][2]);
                acc[i][3] = fma2(a[i], b23.y, acc[i][3]);
            }
        }
        __syncthreads();
    }

    const int jb = j0 + tx * 8;
    float bias[8];
#pragma unroll
    for (int p = 0; p < 8; p++) {
        int j = jb + p;
        bias[p] = b_ih[j] + (j < 512 ? b_hh[j] : 0.0f);
    }
#pragma unroll
    for (int i = 0; i < 8; i++) {
        float o[8];
#pragma unroll
        for (int p = 0; p < 4; p++) {
            float2 v = unpack2(acc[i][p]);
            o[2 * p]     = v.x + bias[2 * p];
            o[2 * p + 1] = v.y + bias[2 * p + 1];
        }
        float* dst = g_GI + (size_t)(r0 + ty * 8 + i) * 768 + jb;
        *(float4*)dst       = make_float4(o[0], o[1], o[2], o[3]);
        *(float4*)(dst + 4) = make_float4(o[4], o[5], o[6], o[7]);
    }
}

// ---------------------------------------------------------------------------
// Recurrent kernel: one CTA per batch b (128 CTAs), 64 rows (=S) per CTA,
// h [64][256] double-buffered in SMEM for all 10 steps.
// Per step, per 64-wide d-chunk: acc_{r,z,hn}[row][d] = h . WhhT columns
// (d, 256+d, 512+d), then fused GRU activation + y readout.
__global__ void __launch_bounds__(256) rnn_kernel(const float* __restrict__ user_embs,
                                                  const float* __restrict__ b_hh,
                                                  const float* __restrict__ w_out,
                                                  const float* __restrict__ b_out,
                                                  const int* __restrict__ length,
                                                  float* __restrict__ out) {
    extern __shared__ float sm[];
    float* hbuf0 = sm;           // 16384 floats
    float* hbuf1 = sm + 16384;   // 16384
    float* wsm   = sm + 32768;   // [32 kk][3 gate][64 j] = 6144
    float* ysm   = sm + 38912;   // 64

    const int b = blockIdx.x;
    const int tid = threadIdx.x;
    const int tx = tid & 15, ty = tid >> 4;  // tx -> d groups, ty -> row groups

    // h0 = user_embs[b, clip(length[b]-1, 0)], broadcast to all 64 rows
    int idx = length[b] - 1;
    if (idx < 0) idx = 0;
    const float* u0 = user_embs + ((size_t)b * 64 + idx) * 256;
#pragma unroll 1
    for (int it = 0; it < 64; it++) {
        int t = tid + it * 256;
        hbuf0[t] = u0[t & 255];
    }
    const float bout = b_out[0];
    float* hcur = hbuf0;
    float* hnxt = hbuf1;

    for (int k = 0; k < 10; k++) {
        if (tid < 64) ysm[tid] = bout;
        float yacc[4] = {0.f, 0.f, 0.f, 0.f};

#pragma unroll 1
        for (int dc = 0; dc < 4; dc++) {
            unsigned long long ar[4][2], az[4][2], an[4][2];
#pragma unroll
            for (int i = 0; i < 4; i++) {
                ar[i][0] = ar[i][1] = 0ull;
                az[i][0] = az[i][1] = 0ull;
                an[i][0] = an[i][1] = 0ull;
            }
#pragma unroll 1
            for (int kt = 0; kt < 8; kt++) {
                __syncthreads();  // protect wsm reuse (also orders h-init / h swap)
#pragma unroll
                for (int it = 0; it < 6; it++) {
                    int f = tid + it * 256;  // 1536 float4s: [32 kk][3 g][16 j4]
                    int kk = f / 48;
                    int rem = f - kk * 48;
                    int g = rem >> 4;
                    int j4 = rem & 15;
                    *(float4*)(wsm + kk * 192 + g * 64 + j4 * 4) =
                        *(const float4*)(g_WhhT + (size_t)(kt * 32 + kk) * 768 +
                                         g * 256 + dc * 64 + j4 * 4);
                }
                __syncthreads();
#pragma unroll
                for (int kk4 = 0; kk4 < 8; kk4++) {
                    float4 av[4];
#pragma unroll
                    for (int i = 0; i < 4; i++)
                        av[i] = *(const float4*)(hcur + (ty * 4 + i) * 256 +
                                                 kt * 32 + kk4 * 4);
                    const float* avf = (const float*)av;
#pragma unroll
                    for (int c = 0; c < 4; c++) {
                        const int kk = kk4 * 4 + c;
                        ulonglong2 br = *(ulonglong2*)(wsm + kk * 192 + tx * 4);
                        ulonglong2 bz = *(ulonglong2*)(wsm + kk * 192 + 64 + tx * 4);
                        ulonglong2 bn = *(ulonglong2*)(wsm + kk * 192 + 128 + tx * 4);
#pragma unroll
                        for (int i = 0; i < 4; i++) {
                            unsigned long long a2 = pack2(avf[i * 4 + c], avf[i * 4 + c]);
                            ar[i][0] = fma2(a2, br.x, ar[i][0]);
                            ar[i][1] = fma2(a2, br.y, ar[i][1]);
                            az[i][0] = fma2(a2, bz.x, az[i][0]);
                            az[i][1] = fma2(a2, bz.y, az[i][1]);
                            an[i][0] = fma2(a2, bn.x, an[i][0]);
                            an[i][1] = fma2(a2, bn.y, an[i][1]);
                        }
                    }
                }
            }

            // fused GRU activation for this 64-wide d-chunk
            const int d = dc * 64 + tx * 4;
            float4 bh4 = *(const float4*)(b_hh + 512 + d);
            float4 wo4 = *(const float4*)(w_out + d);
            const float* bhf = (const float*)&bh4;
            const float* wof = (const float*)&wo4;
#pragma unroll
            for (int i = 0; i < 4; i++) {
                const int row = ty * 4 + i;
                const int n = b * 64 + row;
                const float* gi = g_GI + (size_t)(n * 10 + k) * 768;
                float4 gr4 = *(const float4*)(gi + d);
                float4 gz4 = *(const float4*)(gi + 256 + d);
                float4 gn4 = *(const float4*)(gi + 512 + d);
                float4 ho4 = *(const float4*)(hcur + row * 256 + d);
                const float* grf = (const float*)&gr4;
                const float* gzf = (const float*)&gz4;
                const float* gnf = (const float*)&gn4;
                const float* hof = (const float*)&ho4;
                float arf[4], azf[4], anf[4];
                float2 p;
                p = unpack2(ar[i][0]); arf[0] = p.x; arf[1] = p.y;
                p = unpack2(ar[i][1]); arf[2] = p.x; arf[3] = p.y;
                p = unpack2(az[i][0]); azf[0] = p.x; azf[1] = p.y;
                p = unpack2(az[i][1]); azf[2] = p.x; azf[3] = p.y;
                p = unpack2(an[i][0]); anf[0] = p.x; anf[1] = p.y;
                p = unpack2(an[i][1]); anf[2] = p.x; anf[3] = p.y;
                float hv[4];
#pragma unroll
                for (int c = 0; c < 4; c++) {
                    float r = 1.0f / (1.0f + expf(-(grf[c] + arf[c])));
                    float z = 1.0f / (1.0f + expf(-(gzf[c] + azf[c])));
                    float hn = anf[c] + bhf[c];
                    float nv = tanhf(gnf[c] + r * hn);
                    hv[c] = (1.0f - z) * nv + z * hof[c];
                    yacc[i] += hv[c] * wof[c];
                }
                *(float4*)(hnxt + row * 256 + d) = make_float4(hv[0], hv[1], hv[2], hv[3]);
            }
        }

        // y readout reduction across d (threads sharing a row)
#pragma unroll
        for (int i = 0; i < 4; i++) atomicAdd(&ysm[ty * 4 + i], yacc[i]);
        __syncthreads();
        if (tid < 64) out[(size_t)(b * 64 + tid) * 10 + k] = ysm[tid];
        float* tmp = hcur; hcur = hnxt; hnxt = tmp;
        __syncthreads();
    }
}

// ---------------------------------------------------------------------------
extern "C" void kernel_launch(void* const* d_in, const int* in_sizes, int n_in,
                              void* d_out, int out_size) {
    (void)in_sizes; (void)n_in; (void)out_size;
    const float* item_embs = (const float*)d_in[0];  // [128,64,10,256]
    const float* user_embs = (const float*)d_in[1];  // [128,64,256]
    const float* W_ih      = (const float*)d_in[2];  // [768,512]
    const float* W_hh      = (const float*)d_in[3];  // [768,256]
    const float* b_ih      = (const float*)d_in[4];  // [768]
    const float* b_hh      = (const float*)d_in[5];  // [768]
    const float* w_out     = (const float*)d_in[6];  // [256]
    const float* b_out     = (const float*)d_in[7];  // scalar
    const int*   length    = (const int*)d_in[8];    // [128]
    float* out = (float*)d_out;                      // [128,64,10]

    prep_kernel<<<768, 256>>>(W_ih, W_hh);

    dim3 gg(640, 6);  // 81920/128 x 768/128
    gi_gemm<<<gg, 256>>>(item_embs, b_ih, b_hh);

    const int smem = (2 * 64 * 256 + 32 * 192 + 64) * 4;  // 155,904 B
    cudaFuncSetAttribute(rnn_kernel, cudaFuncAttributeMaxDynamicSharedMemorySize, smem);
    rnn_kernel<<<128, 256, smem>>>(user_embs, b_hh, w_out, b_out, length, out);
}